// round 12
// baseline (speedup 1.0000x reference)
#include <cuda_runtime.h>
#include <cuda_fp16.h>
#include <cstdint>

#define BATCH 32
#define FEAT  1024
#define PROJ  256
#define NSUP  8192
#define NCLS  1000

// ---- scratch (no allocations allowed; __device__ globals) ----
__device__ float g_xq[BATCH * PROJ];
__device__ float g_lh[2 * BATCH * NSUP];         // 2 MB: per-proj-half logits
__device__ int   g_sy_is64;
// B in mma-fragment order: idx = ks*512 + half*256 + wn*128 + np*32 + lane
__device__ uint4 g_wfrag[128 * 512];             // 1 MB

__device__ __forceinline__ uint32_t smem_u32(const void* p) {
    uint32_t a;
    asm("{ .reg .u64 t; cvta.to.shared.u64 t, %1; cvt.u32.u64 %0, t; }"
        : "=r"(a) : "l"(p));
    return a;
}

// ---------------------------------------------------------------------------
// K0: detect int64 vs int32 sy
// ---------------------------------------------------------------------------
__global__ void k_detect(const unsigned* __restrict__ w) {
    __shared__ int nz;
    if (threadIdx.x == 0) nz = 0;
    __syncthreads();
    int f = 0;
    for (int i = threadIdx.x; i < 4096; i += 256)
        if (w[2 * i + 1] != 0u) f = 1;
    if (f) atomicOr(&nz, 1);
    __syncthreads();
    if (threadIdx.x == 0) g_sy_is64 = (nz == 0) ? 1 : 0;
}

// ---------------------------------------------------------------------------
__device__ __forceinline__ uint32_t hl_pack(float a) {
    __half h = __float2half_rn(a);
    __half l = __float2half_rn(a - __half2float(h));
    __half2 p = __halves2half2(h, l);
    return *(uint32_t*)&p;
}

// ---------------------------------------------------------------------------
// K_wtf: W[1024][256] -> g_wfrag (fp16 h/l pairs in mma B-fragment order)
// ---------------------------------------------------------------------------
__global__ void k_wtf(const float* __restrict__ W) {
    int idx  = blockIdx.x * 256 + threadIdx.x;   // 0..65535
    int lane = idx & 31;
    int np   = (idx >> 5) & 3;
    int wn   = (idx >> 7) & 1;
    int hb   = (idx >> 8) & 1;
    int ks   = idx >> 9;                          // 0..127
    int n0   = hb * 128 + wn * 64 + np * 16 + (lane >> 2);
    int k0   = ks * 8 + (lane & 3);
    uint4 r;
    r.x = hl_pack(W[(size_t)k0 * PROJ + n0]);
    r.y = hl_pack(W[(size_t)(k0 + 4) * PROJ + n0]);
    r.z = hl_pack(W[(size_t)k0 * PROJ + n0 + 8]);
    r.w = hl_pack(W[(size_t)(k0 + 4) * PROJ + n0 + 8]);
    g_wfrag[idx] = r;
}

// ---------------------------------------------------------------------------
// K1: xq = x @ W (32 x 256). grid (32 b, 8 p-chunks), 256 thr = 32 p x 8 kslc.
// ---------------------------------------------------------------------------
__global__ void k_xq2(const float* __restrict__ x, const float* __restrict__ W) {
    __shared__ float red[8][33];
    const int b = blockIdx.x, pc = blockIdx.y;
    const int lane = threadIdx.x & 31, ks = threadIdx.x >> 5;
    const int p = pc * 32 + lane;
    float a0 = 0.f, a1 = 0.f, a2 = 0.f, a3 = 0.f;
    const float* xr = x + b * FEAT + ks * 128;
    const float* wr = W + (size_t)(ks * 128) * PROJ + p;
#pragma unroll 8
    for (int k = 0; k < 128; k += 4) {
        a0 = fmaf(xr[k + 0], wr[(k + 0) * PROJ], a0);
        a1 = fmaf(xr[k + 1], wr[(k + 1) * PROJ], a1);
        a2 = fmaf(xr[k + 2], wr[(k + 2) * PROJ], a2);
        a3 = fmaf(xr[k + 3], wr[(k + 3) * PROJ], a3);
    }
    red[ks][lane] = (a0 + a1) + (a2 + a3);
    __syncthreads();
    if (ks == 0) {
        float s = 0.f;
#pragma unroll
        for (int q = 0; q < 8; q++) s += red[q][lane];
        g_xq[b * PROJ + p] = s;
    }
}

// ---------------------------------------------------------------------------
// K2: sxp GEMM (HMMA fp16 2-slot K-doubling) + fused logits epilogue.
// 256 thr / 8 warps (4M x 2N), warp tile 32x64, CTA 128x128, grid (64, 2).
// Warp-private A staging (no CTA barriers in mainloop) with DEPTH-2 raw-A
// register prefetch: chunk ch loads raw(ch+2), expands raw(ch+1) -> the
// LDG->expand gap spans ~2 chunks, covering DRAM latency.
// B via LDG.128 of precomputed fragments (depth-1 register prefetch).
// ---------------------------------------------------------------------------
#define BANDB  2560                   // 32 rows * 80 B per warp per stage
#define STG2B  20480                  // 8 warps * BANDB
#define TS_PITCH  132
#define XQT_OFF   67584               // 128*132*4
#define XQT_PITCH 36
#define SSQ_OFF   86016               // XQT_OFF + 128*36*4
#define DYNB      86528

__global__ void __launch_bounds__(256, 1)
k_sxp_hmma(const float* __restrict__ sx) {
    extern __shared__ __align__(16) char dyn[];

    const int tid  = threadIdx.x;
    const int lane = tid & 31;
    const int wid  = tid >> 5;
    const int wm   = wid & 3;        // M block (32 rows)
    const int wn   = wid >> 2;       // N block (64 cols)
    const int bs   = blockIdx.x * 128;
    const int bn   = blockIdx.y * 128;
    const int hb   = blockIdx.y;

    const uint32_t sbase = smem_u32(dyn);
    const uint32_t pw_u32[2] = {sbase + (uint32_t)wid * BANDB,
                                sbase + STG2B + (uint32_t)wid * BANDB};
    char* pw_ptr[2] = {dyn + wid * BANDB, dyn + STG2B + wid * BANDB};

    // A load coords (warp-private band): iter i (0..3):
    //   local row = i*8 + (lane>>2), float4 col = lane&3
    const int arow = lane >> 2;      // 0..7
    const int aq   = lane & 3;       // 0..3
    const float* aptr[4];
#pragma unroll
    for (int i = 0; i < 4; i++)
        aptr[i] = sx + (size_t)(bs + wm * 32 + i * 8 + arow) * FEAT + aq * 4;
    const uint32_t sts_off = (uint32_t)(arow * 80 + aq * 16);

    // B fragment pointer: idx = ks*512 + hb*256 + wn*128 + np*32 + lane
    const uint4* bbase = g_wfrag + hb * 256 + wn * 128 + lane;

    float c[2][8][4];
#pragma unroll
    for (int t = 0; t < 2; t++)
#pragma unroll
        for (int n = 0; n < 8; n++)
#pragma unroll
            for (int e = 0; e < 4; e++) c[t][n][e] = 0.f;

    const int grp  = lane >> 3;
    const int rsel = lane & 7;
    const int a_row_off = ((grp & 1) << 3) + rsel;
    const int a_u_off   = (grp >> 1) & 1;

    auto expand = [](float4 v) -> uint4 {
        __half h0 = __float2half_rn(v.x), h1 = __float2half_rn(v.y);
        __half h2 = __float2half_rn(v.z), h3 = __float2half_rn(v.w);
        __half2 p0 = __halves2half2(h0, __float2half_rn(v.x - __half2float(h0)));
        __half2 p1 = __halves2half2(h1, __float2half_rn(v.y - __half2float(h1)));
        __half2 p2 = __halves2half2(h2, __float2half_rn(v.z - __half2float(h2)));
        __half2 p3 = __halves2half2(h3, __float2half_rn(v.w - __half2float(h3)));
        return make_uint4(*(uint32_t*)&p0, *(uint32_t*)&p1,
                          *(uint32_t*)&p2, *(uint32_t*)&p3);
    };

    uint4  bcur[2][4];    // B fragments for current chunk [ks][np]
    float4 av[2][4];      // raw A banks: chunk c lives in bank c&1

    // ---- prologue ----
    {
        // raw(0) -> expand -> stage 0
        float4 a0[4];
#pragma unroll
        for (int i = 0; i < 4; i++) a0[i] = *(const float4*)(aptr[i]);
#pragma unroll
        for (int i = 0; i < 4; i++)
            *(uint4*)(pw_ptr[0] + i * 8 * 80 + sts_off) = expand(a0[i]);
        // raw(1) -> bank 1
#pragma unroll
        for (int i = 0; i < 4; i++) av[1][i] = *(const float4*)(aptr[i] + 16);
        // B(0)
#pragma unroll
        for (int ks = 0; ks < 2; ks++)
#pragma unroll
            for (int np = 0; np < 4; np++)
                bcur[ks][np] = bbase[ks * 512 + np * 32];
    }
    __syncwarp();

#pragma unroll 2
    for (int ch = 0; ch < 64; ch++) {
        const int s = ch & 1;
        uint4 bnx[2][4];

        // 1) issue raw-A LDG for chunk ch+2 into bank ch&1
        if (ch < 62) {
            const int k0 = (ch + 2) * 16;
#pragma unroll
            for (int i = 0; i < 4; i++)
                av[s][i] = *(const float4*)(aptr[i] + k0);
        }
        // 2) issue B LDG for chunk ch+1
        if (ch < 63) {
#pragma unroll
            for (int ks = 0; ks < 2; ks++)
#pragma unroll
                for (int np = 0; np < 4; np++)
                    bnx[ks][np] = bbase[(2 * (ch + 1) + ks) * 512 + np * 32];
        }
        // 3) expand raw(ch+1) (loaded back at ch-1) -> stage ns
        if (ch < 63) {
            const int ns = s ^ 1;
#pragma unroll
            for (int i = 0; i < 4; i++)
                *(uint4*)(pw_ptr[ns] + i * 8 * 80 + sts_off) = expand(av[ns][i]);
        }

        // 4) compute chunk ch on stage s
#pragma unroll
        for (int ks = 0; ks < 2; ks++) {
            uint32_t af[2][4];
#pragma unroll
            for (int t = 0; t < 2; t++) {
                int row = t * 16 + a_row_off;
                uint32_t addr = pw_u32[s] + (uint32_t)(row * 80 + (2 * ks + a_u_off) * 16);
                asm volatile(
                    "ldmatrix.sync.aligned.m8n8.x4.shared.b16 {%0,%1,%2,%3}, [%4];"
                    : "=r"(af[t][0]), "=r"(af[t][1]), "=r"(af[t][2]), "=r"(af[t][3])
                    : "r"(addr));
            }
#pragma unroll
            for (int t = 0; t < 2; t++)
#pragma unroll
                for (int nf = 0; nf < 8; nf++) {
                    const uint4& bq = bcur[ks][nf >> 1];
                    uint32_t b0 = (nf & 1) ? bq.z : bq.x;
                    uint32_t b1 = (nf & 1) ? bq.w : bq.y;
                    asm volatile(
                        "mma.sync.aligned.m16n8k16.row.col.f32.f16.f16.f32 "
                        "{%0,%1,%2,%3}, {%4,%5,%6,%7}, {%8,%9}, {%0,%1,%2,%3};"
                        : "+f"(c[t][nf][0]), "+f"(c[t][nf][1]),
                          "+f"(c[t][nf][2]), "+f"(c[t][nf][3])
                        : "r"(af[t][0]), "r"(af[t][1]), "r"(af[t][2]), "r"(af[t][3]),
                          "r"(b0), "r"(b1));
                }
        }

        // 5) roll B, sync the warp-private stage
        if (ch < 63) {
#pragma unroll
            for (int ks = 0; ks < 2; ks++)
#pragma unroll
                for (int np = 0; np < 4; np++)
                    bcur[ks][np] = bnx[ks][np];
            __syncwarp();
        }
    }

    // ================= fused logits epilogue =================
    __syncthreads();   // all warps done with staging; reuse smem
    float* Ts   = (float*)dyn;               // [128][132] sxp tile
    float* xqT  = (float*)(dyn + XQT_OFF);   // [128][36]  xq half, transposed
    float* ssqh = (float*)(dyn + SSQ_OFF);   // [128]

    // spill fragments: Ts[j = local support][k = local proj]
#pragma unroll
    for (int t = 0; t < 2; t++) {
        int r0 = wm * 32 + t * 16 + (lane >> 2);
        int cl = wn * 64 + 2 * (lane & 3);
#pragma unroll
        for (int nf = 0; nf < 8; nf++) {
            *(float2*)&Ts[r0 * TS_PITCH + cl + nf * 8] =
                make_float2(c[t][nf][0], c[t][nf][1]);
            *(float2*)&Ts[(r0 + 8) * TS_PITCH + cl + nf * 8] =
                make_float2(c[t][nf][2], c[t][nf][3]);
        }
    }
    // load xq half transposed: xqT[k][b]
    for (int i = tid; i < 32 * 128; i += 256) {
        int b = i & 31, k = i >> 5;
        xqT[k * XQT_PITCH + b] = g_xq[b * PROJ + bn + k];
    }
    __syncthreads();

    // ssq_half[j]
    if (tid < 128) {
        float s = 0.f;
        const float4* row = (const float4*)&Ts[tid * TS_PITCH];
#pragma unroll
        for (int q = 0; q < 32; q++) {
            float4 v = row[q];
            s += v.x * v.x + v.y * v.y + v.z * v.z + v.w * v.w;
        }
        ssqh[tid] = s;
    }
    __syncthreads();

    // partial logits: 4 j x 4 b per thread; coalesced float4 stores along j
    {
        const int j0 = (tid & 31) * 4;        // 0..124
        const int b0 = (tid >> 5) * 4;        // 0..28
        float acc[4][4];
#pragma unroll
        for (int a = 0; a < 4; a++)
#pragma unroll
            for (int b = 0; b < 4; b++) acc[a][b] = 0.f;

        for (int k = 0; k < 128; k += 4) {
            float4 xv[4];
#pragma unroll
            for (int kk = 0; kk < 4; kk++)
                xv[kk] = *(const float4*)&xqT[(k + kk) * XQT_PITCH + b0];
#pragma unroll
            for (int jj = 0; jj < 4; jj++) {
                float4 tv = *(const float4*)&Ts[(j0 + jj) * TS_PITCH + k];
                float tk[4] = {tv.x, tv.y, tv.z, tv.w};
#pragma unroll
                for (int kk = 0; kk < 4; kk++) {
                    acc[jj][0] = fmaf(tk[kk], xv[kk].x, acc[jj][0]);
                    acc[jj][1] = fmaf(tk[kk], xv[kk].y, acc[jj][1]);
                    acc[jj][2] = fmaf(tk[kk], xv[kk].z, acc[jj][2]);
                    acc[jj][3] = fmaf(tk[kk], xv[kk].w, acc[jj][3]);
                }
            }
        }
        float4 sq = *(const float4*)&ssqh[j0];
        float sqa[4] = {sq.x, sq.y, sq.z, sq.w};
#pragma unroll
        for (int bb = 0; bb < 4; bb++) {
            float4 o;
            o.x = 2.f * acc[0][bb] - sqa[0];
            o.y = 2.f * acc[1][bb] - sqa[1];
            o.z = 2.f * acc[2][bb] - sqa[2];
            o.w = 2.f * acc[3][bb] - sqa[3];
            *(float4*)&g_lh[((size_t)hb * BATCH + b0 + bb) * NSUP + bs + j0] = o;
        }
    }
}

// ---------------------------------------------------------------------------
// K5: per-row softmax + class scatter + log (sums the two proj-half logits)
// ---------------------------------------------------------------------------
__global__ void __launch_bounds__(1024) k_out(const int* __restrict__ syw,
                                              float* __restrict__ out) {
    const int b = blockIdx.x;
    __shared__ float red[32];
    __shared__ float cls[NCLS];
    const int tid  = threadIdx.x;
    const int warp = tid >> 5, lane = tid & 31;

    for (int c = tid; c < NCLS; c += 1024) cls[c] = 0.f;

    const float* lr0 = g_lh + (size_t)b * NSUP;
    const float* lr1 = g_lh + (size_t)(BATCH + b) * NSUP;
    float l[8];
    float m = -3.4e38f;
#pragma unroll
    for (int q = 0; q < 8; q++) {
        int j = q * 1024 + tid;
        l[q] = lr0[j] + lr1[j];
        m = fmaxf(m, l[q]);
    }
#pragma unroll
    for (int o = 16; o; o >>= 1) m = fmaxf(m, __shfl_xor_sync(0xffffffffu, m, o));
    if (lane == 0) red[warp] = m;
    __syncthreads();
    if (warp == 0) {
        float v = red[lane];
#pragma unroll
        for (int o = 16; o; o >>= 1) v = fmaxf(v, __shfl_xor_sync(0xffffffffu, v, o));
        if (lane == 0) red[0] = v;
    }
    __syncthreads();
    m = red[0];
    __syncthreads();

    float e[8];
    float s = 0.f;
#pragma unroll
    for (int q = 0; q < 8; q++) {
        e[q] = expf(l[q] - m);
        s += e[q];
    }
#pragma unroll
    for (int o = 16; o; o >>= 1) s += __shfl_xor_sync(0xffffffffu, s, o);
    if (lane == 0) red[warp] = s;
    __syncthreads();
    if (warp == 0) {
        float v = red[lane];
#pragma unroll
        for (int o = 16; o; o >>= 1) v += __shfl_xor_sync(0xffffffffu, v, o);
        if (lane == 0) red[0] = v;
    }
    __syncthreads();
    const float invZ = 1.f / red[0];
    const int is64 = g_sy_is64;

#pragma unroll
    for (int q = 0; q < 8; q++) {
        int j = q * 1024 + tid;
        int cidx = is64 ? syw[2 * j] : syw[j];
        atomicAdd(&cls[cidx], e[q]);
    }
    __syncthreads();
    for (int c = tid; c < NCLS; c += 1024)
        out[b * NCLS + c] = logf(cls[c] * invZ + 1e-12f);
}

// ---------------------------------------------------------------------------
extern "C" void kernel_launch(void* const* d_in, const int* in_sizes, int n_in,
                              void* d_out, int out_size) {
    const float* x = nullptr;
    const float* sx = nullptr;
    const float* W = nullptr;
    const void*  sy = nullptr;
    for (int i = 0; i < n_in; i++) {
        switch (in_sizes[i]) {
            case BATCH * FEAT: x  = (const float*)d_in[i]; break;
            case NSUP * FEAT:  sx = (const float*)d_in[i]; break;
            case FEAT * PROJ:  W  = (const float*)d_in[i]; break;
            case NSUP:         sy = d_in[i];               break;
            default: break;
        }
    }
    float* out = (float*)d_out;

    static int smem_set = 0;
    if (!smem_set) {
        cudaFuncSetAttribute(k_sxp_hmma,
                             cudaFuncAttributeMaxDynamicSharedMemorySize, DYNB);
        smem_set = 1;
    }

    k_detect<<<1, 256>>>((const unsigned*)sy);
    k_wtf<<<256, 256>>>(W);
    k_xq2<<<dim3(32, 8), 256>>>(x, W);
    k_sxp_hmma<<<dim3(64, 2), 256, DYNB>>>(sx);
    k_out<<<BATCH, 1024>>>((const int*)sy, out);
}

// round 13
// speedup vs baseline: 1.1761x; 1.1761x over previous
#include <cuda_runtime.h>
#include <cuda_fp16.h>
#include <cstdint>

#define BATCH 32
#define FEAT  1024
#define PROJ  256
#define NSUP  8192
#define NCLS  1000

// ---- scratch (no allocations allowed; __device__ globals) ----
__device__ float g_xq[BATCH * PROJ];
__device__ float g_lh[2 * BATCH * NSUP];         // 2 MB: per-proj-half logits
__device__ int   g_sy_is64;
// B in mma-fragment order: idx = ks*512 + half*256 + wn*128 + np*32 + lane
__device__ uint4 g_wfrag[128 * 512];             // 1 MB

__device__ __forceinline__ uint32_t smem_u32(const void* p) {
    uint32_t a;
    asm("{ .reg .u64 t; cvta.to.shared.u64 t, %1; cvt.u32.u64 %0, t; }"
        : "=r"(a) : "l"(p));
    return a;
}

__device__ __forceinline__ uint32_t hl_pack(float a) {
    __half h = __float2half_rn(a);
    __half l = __float2half_rn(a - __half2float(h));
    __half2 p = __halves2half2(h, l);
    return *(uint32_t*)&p;
}

// ---------------------------------------------------------------------------
// K_pre: one launch doing three independent jobs.
//  blocks 0..255   : W[1024][256] -> g_wfrag (mma B-fragment order)
//  blocks 256..511 : xq = x @ W   (the old k_xq2 grid(32,8) flattened)
//  block  512      : detect int64 vs int32 sy
// ---------------------------------------------------------------------------
__global__ void __launch_bounds__(256) k_pre(const float* __restrict__ W,
                                             const float* __restrict__ x,
                                             const unsigned* __restrict__ syw) {
    const int bx = blockIdx.x;
    if (bx < 256) {
        // ---- wfrag build ----
        int idx  = bx * 256 + threadIdx.x;   // 0..65535
        int lane = idx & 31;
        int np   = (idx >> 5) & 3;
        int wn   = (idx >> 7) & 1;
        int hb   = (idx >> 8) & 1;
        int ks   = idx >> 9;                 // 0..127
        int n0   = hb * 128 + wn * 64 + np * 16 + (lane >> 2);
        int k0   = ks * 8 + (lane & 3);
        uint4 r;
        r.x = hl_pack(W[(size_t)k0 * PROJ + n0]);
        r.y = hl_pack(W[(size_t)(k0 + 4) * PROJ + n0]);
        r.z = hl_pack(W[(size_t)k0 * PROJ + n0 + 8]);
        r.w = hl_pack(W[(size_t)(k0 + 4) * PROJ + n0 + 8]);
        g_wfrag[idx] = r;
    } else if (bx < 512) {
        // ---- xq GEMV block (identical math to old k_xq2) ----
        __shared__ float red[8][33];
        const int blk = bx - 256;            // 0..255
        const int b = blk >> 3, pc = blk & 7;
        const int lane = threadIdx.x & 31, ks = threadIdx.x >> 5;
        const int p = pc * 32 + lane;
        float a0 = 0.f, a1 = 0.f, a2 = 0.f, a3 = 0.f;
        const float* xr = x + b * FEAT + ks * 128;
        const float* wr = W + (size_t)(ks * 128) * PROJ + p;
#pragma unroll 8
        for (int k = 0; k < 128; k += 4) {
            a0 = fmaf(xr[k + 0], wr[(k + 0) * PROJ], a0);
            a1 = fmaf(xr[k + 1], wr[(k + 1) * PROJ], a1);
            a2 = fmaf(xr[k + 2], wr[(k + 2) * PROJ], a2);
            a3 = fmaf(xr[k + 3], wr[(k + 3) * PROJ], a3);
        }
        red[ks][lane] = (a0 + a1) + (a2 + a3);
        __syncthreads();
        if (ks == 0) {
            float s = 0.f;
#pragma unroll
            for (int q = 0; q < 8; q++) s += red[q][lane];
            g_xq[b * PROJ + p] = s;
        }
    } else {
        // ---- sy dtype detect ----
        __shared__ int nz;
        if (threadIdx.x == 0) nz = 0;
        __syncthreads();
        int f = 0;
        for (int i = threadIdx.x; i < 4096; i += 256)
            if (syw[2 * i + 1] != 0u) f = 1;
        if (f) atomicOr(&nz, 1);
        __syncthreads();
        if (threadIdx.x == 0) g_sy_is64 = (nz == 0) ? 1 : 0;
    }
}

// ---------------------------------------------------------------------------
// K2: sxp GEMM (HMMA fp16 2-slot K-doubling) + fused logits epilogue.
// 256 thr / 8 warps (4M x 2N), warp tile 32x64, CTA 128x128, grid (64, 2).
// Warp-private A staging: each warp loads/expands/stores its OWN 32-row band
// into private smem -> NO __syncthreads in the mainloop, only __syncwarp.
// B via LDG.128 of precomputed fragments (register prefetch).  [R11 exact]
// ---------------------------------------------------------------------------
#define BANDB  2560                   // 32 rows * 80 B per warp per stage
#define STG2B  20480                  // 8 warps * BANDB
#define TS_PITCH  132
#define XQT_OFF   67584               // 128*132*4
#define XQT_PITCH 36
#define SSQ_OFF   86016               // XQT_OFF + 128*36*4
#define DYNB      86528

__global__ void __launch_bounds__(256, 1)
k_sxp_hmma(const float* __restrict__ sx) {
    extern __shared__ __align__(16) char dyn[];

    const int tid  = threadIdx.x;
    const int lane = tid & 31;
    const int wid  = tid >> 5;
    const int wm   = wid & 3;        // M block (32 rows)
    const int wn   = wid >> 2;       // N block (64 cols)
    const int bs   = blockIdx.x * 128;
    const int bn   = blockIdx.y * 128;
    const int hb   = blockIdx.y;

    const uint32_t sbase = smem_u32(dyn);
    const uint32_t pw_u32[2] = {sbase + (uint32_t)wid * BANDB,
                                sbase + STG2B + (uint32_t)wid * BANDB};
    char* pw_ptr[2] = {dyn + wid * BANDB, dyn + STG2B + wid * BANDB};

    const int arow = lane >> 2;      // 0..7
    const int aq   = lane & 3;       // 0..3
    const float* aptr[4];
#pragma unroll
    for (int i = 0; i < 4; i++)
        aptr[i] = sx + (size_t)(bs + wm * 32 + i * 8 + arow) * FEAT + aq * 4;
    const uint32_t sts_off = (uint32_t)(arow * 80 + aq * 16);

    const uint4* bbase = g_wfrag + hb * 256 + wn * 128 + lane;

    float c[2][8][4];
#pragma unroll
    for (int t = 0; t < 2; t++)
#pragma unroll
        for (int n = 0; n < 8; n++)
#pragma unroll
            for (int e = 0; e < 4; e++) c[t][n][e] = 0.f;

    const int grp  = lane >> 3;
    const int rsel = lane & 7;
    const int a_row_off = ((grp & 1) << 3) + rsel;
    const int a_u_off   = (grp >> 1) & 1;

    auto expand = [](float4 v) -> uint4 {
        __half h0 = __float2half_rn(v.x), h1 = __float2half_rn(v.y);
        __half h2 = __float2half_rn(v.z), h3 = __float2half_rn(v.w);
        __half2 p0 = __halves2half2(h0, __float2half_rn(v.x - __half2float(h0)));
        __half2 p1 = __halves2half2(h1, __float2half_rn(v.y - __half2float(h1)));
        __half2 p2 = __halves2half2(h2, __float2half_rn(v.z - __half2float(h2)));
        __half2 p3 = __halves2half2(h3, __float2half_rn(v.w - __half2float(h3)));
        return make_uint4(*(uint32_t*)&p0, *(uint32_t*)&p1,
                          *(uint32_t*)&p2, *(uint32_t*)&p3);
    };

    uint4 bcur[2][4];    // [ks][np]

    // ---- prologue: chunk 0 into stage 0 ----
    {
        float4 av[4];
#pragma unroll
        for (int i = 0; i < 4; i++) av[i] = *(const float4*)(aptr[i]);
#pragma unroll
        for (int i = 0; i < 4; i++)
            *(uint4*)(pw_ptr[0] + i * 8 * 80 + sts_off) = expand(av[i]);
#pragma unroll
        for (int ks = 0; ks < 2; ks++)
#pragma unroll
            for (int np = 0; np < 4; np++)
                bcur[ks][np] = bbase[ks * 512 + np * 32];
    }
    __syncwarp();

#pragma unroll 2
    for (int ch = 0; ch < 64; ch++) {
        const int s = ch & 1;
        float4 av[4];
        uint4  bnx[2][4];
        if (ch < 63) {
            const int k0 = (ch + 1) * 16;
#pragma unroll
            for (int i = 0; i < 4; i++)
                av[i] = *(const float4*)(aptr[i] + k0);
#pragma unroll
            for (int ks = 0; ks < 2; ks++)
#pragma unroll
                for (int np = 0; np < 4; np++)
                    bnx[ks][np] = bbase[(2 * (ch + 1) + ks) * 512 + np * 32];
        }

        // ---- compute on stage s: 2 ksteps of 16 expanded k ----
#pragma unroll
        for (int ks = 0; ks < 2; ks++) {
            uint32_t af[2][4];
#pragma unroll
            for (int t = 0; t < 2; t++) {
                int row = t * 16 + a_row_off;
                uint32_t addr = pw_u32[s] + (uint32_t)(row * 80 + (2 * ks + a_u_off) * 16);
                asm volatile(
                    "ldmatrix.sync.aligned.m8n8.x4.shared.b16 {%0,%1,%2,%3}, [%4];"
                    : "=r"(af[t][0]), "=r"(af[t][1]), "=r"(af[t][2]), "=r"(af[t][3])
                    : "r"(addr));
            }
#pragma unroll
            for (int t = 0; t < 2; t++)
#pragma unroll
                for (int nf = 0; nf < 8; nf++) {
                    const uint4& bq = bcur[ks][nf >> 1];
                    uint32_t b0 = (nf & 1) ? bq.z : bq.x;
                    uint32_t b1 = (nf & 1) ? bq.w : bq.y;
                    asm volatile(
                        "mma.sync.aligned.m16n8k16.row.col.f32.f16.f16.f32 "
                        "{%0,%1,%2,%3}, {%4,%5,%6,%7}, {%8,%9}, {%0,%1,%2,%3};"
                        : "+f"(c[t][nf][0]), "+f"(c[t][nf][1]),
                          "+f"(c[t][nf][2]), "+f"(c[t][nf][3])
                        : "r"(af[t][0]), "r"(af[t][1]), "r"(af[t][2]), "r"(af[t][3]),
                          "r"(b0), "r"(b1));
                }
        }

        if (ch < 63) {
            const int ns = s ^ 1;
#pragma unroll
            for (int i = 0; i < 4; i++)
                *(uint4*)(pw_ptr[ns] + i * 8 * 80 + sts_off) = expand(av[i]);
#pragma unroll
            for (int ks = 0; ks < 2; ks++)
#pragma unroll
                for (int np = 0; np < 4; np++)
                    bcur[ks][np] = bnx[ks][np];
            __syncwarp();
        }
    }

    // ================= fused logits epilogue =================
    __syncthreads();   // all warps done with staging; reuse smem
    float* Ts   = (float*)dyn;               // [128][132] sxp tile
    float* xqT  = (float*)(dyn + XQT_OFF);   // [128][36]  xq half, transposed
    float* ssqh = (float*)(dyn + SSQ_OFF);   // [128]

#pragma unroll
    for (int t = 0; t < 2; t++) {
        int r0 = wm * 32 + t * 16 + (lane >> 2);
        int cl = wn * 64 + 2 * (lane & 3);
#pragma unroll
        for (int nf = 0; nf < 8; nf++) {
            *(float2*)&Ts[r0 * TS_PITCH + cl + nf * 8] =
                make_float2(c[t][nf][0], c[t][nf][1]);
            *(float2*)&Ts[(r0 + 8) * TS_PITCH + cl + nf * 8] =
                make_float2(c[t][nf][2], c[t][nf][3]);
        }
    }
    for (int i = tid; i < 32 * 128; i += 256) {
        int b = i & 31, k = i >> 5;
        xqT[k * XQT_PITCH + b] = g_xq[b * PROJ + bn + k];
    }
    __syncthreads();

    if (tid < 128) {
        float s = 0.f;
        const float4* row = (const float4*)&Ts[tid * TS_PITCH];
#pragma unroll
        for (int q = 0; q < 32; q++) {
            float4 v = row[q];
            s += v.x * v.x + v.y * v.y + v.z * v.z + v.w * v.w;
        }
        ssqh[tid] = s;
    }
    __syncthreads();

    {
        const int j0 = (tid & 31) * 4;        // 0..124
        const int b0 = (tid >> 5) * 4;        // 0..28
        float acc[4][4];
#pragma unroll
        for (int a = 0; a < 4; a++)
#pragma unroll
            for (int b = 0; b < 4; b++) acc[a][b] = 0.f;

        for (int k = 0; k < 128; k += 4) {
            float4 xv[4];
#pragma unroll
            for (int kk = 0; kk < 4; kk++)
                xv[kk] = *(const float4*)&xqT[(k + kk) * XQT_PITCH + b0];
#pragma unroll
            for (int jj = 0; jj < 4; jj++) {
                float4 tv = *(const float4*)&Ts[(j0 + jj) * TS_PITCH + k];
                float tk[4] = {tv.x, tv.y, tv.z, tv.w};
#pragma unroll
                for (int kk = 0; kk < 4; kk++) {
                    acc[jj][0] = fmaf(tk[kk], xv[kk].x, acc[jj][0]);
                    acc[jj][1] = fmaf(tk[kk], xv[kk].y, acc[jj][1]);
                    acc[jj][2] = fmaf(tk[kk], xv[kk].z, acc[jj][2]);
                    acc[jj][3] = fmaf(tk[kk], xv[kk].w, acc[jj][3]);
                }
            }
        }
        float4 sq = *(const float4*)&ssqh[j0];
        float sqa[4] = {sq.x, sq.y, sq.z, sq.w};
#pragma unroll
        for (int bb = 0; bb < 4; bb++) {
            float4 o;
            o.x = 2.f * acc[0][bb] - sqa[0];
            o.y = 2.f * acc[1][bb] - sqa[1];
            o.z = 2.f * acc[2][bb] - sqa[2];
            o.w = 2.f * acc[3][bb] - sqa[3];
            *(float4*)&g_lh[((size_t)hb * BATCH + b0 + bb) * NSUP + bs + j0] = o;
        }
    }
}

// ---------------------------------------------------------------------------
// K5: per-row softmax + class scatter + log (sums the two proj-half logits)
// ---------------------------------------------------------------------------
__global__ void __launch_bounds__(1024) k_out(const int* __restrict__ syw,
                                              float* __restrict__ out) {
    const int b = blockIdx.x;
    __shared__ float red[32];
    __shared__ float cls[NCLS];
    const int tid  = threadIdx.x;
    const int warp = tid >> 5, lane = tid & 31;

    for (int c = tid; c < NCLS; c += 1024) cls[c] = 0.f;

    const float* lr0 = g_lh + (size_t)b * NSUP;
    const float* lr1 = g_lh + (size_t)(BATCH + b) * NSUP;
    float l[8];
    float m = -3.4e38f;
#pragma unroll
    for (int q = 0; q < 8; q++) {
        int j = q * 1024 + tid;
        l[q] = lr0[j] + lr1[j];
        m = fmaxf(m, l[q]);
    }
#pragma unroll
    for (int o = 16; o; o >>= 1) m = fmaxf(m, __shfl_xor_sync(0xffffffffu, m, o));
    if (lane == 0) red[warp] = m;
    __syncthreads();
    if (warp == 0) {
        float v = red[lane];
#pragma unroll
        for (int o = 16; o; o >>= 1) v = fmaxf(v, __shfl_xor_sync(0xffffffffu, v, o));
        if (lane == 0) red[0] = v;
    }
    __syncthreads();
    m = red[0];
    __syncthreads();

    float e[8];
    float s = 0.f;
#pragma unroll
    for (int q = 0; q < 8; q++) {
        e[q] = expf(l[q] - m);
        s += e[q];
    }
#pragma unroll
    for (int o = 16; o; o >>= 1) s += __shfl_xor_sync(0xffffffffu, s, o);
    if (lane == 0) red[warp] = s;
    __syncthreads();
    if (warp == 0) {
        float v = red[lane];
#pragma unroll
        for (int o = 16; o; o >>= 1) v += __shfl_xor_sync(0xffffffffu, v, o);
        if (lane == 0) red[0] = v;
    }
    __syncthreads();
    const float invZ = 1.f / red[0];
    const int is64 = g_sy_is64;

#pragma unroll
    for (int q = 0; q < 8; q++) {
        int j = q * 1024 + tid;
        int cidx = is64 ? syw[2 * j] : syw[j];
        atomicAdd(&cls[cidx], e[q]);
    }
    __syncthreads();
    for (int c = tid; c < NCLS; c += 1024)
        out[b * NCLS + c] = logf(cls[c] * invZ + 1e-12f);
}

// ---------------------------------------------------------------------------
extern "C" void kernel_launch(void* const* d_in, const int* in_sizes, int n_in,
                              void* d_out, int out_size) {
    const float* x = nullptr;
    const float* sx = nullptr;
    const float* W = nullptr;
    const void*  sy = nullptr;
    for (int i = 0; i < n_in; i++) {
        switch (in_sizes[i]) {
            case BATCH * FEAT: x  = (const float*)d_in[i]; break;
            case NSUP * FEAT:  sx = (const float*)d_in[i]; break;
            case FEAT * PROJ:  W  = (const float*)d_in[i]; break;
            case NSUP:         sy = d_in[i];               break;
            default: break;
        }
    }
    float* out = (float*)d_out;

    static int smem_set = 0;
    if (!smem_set) {
        cudaFuncSetAttribute(k_sxp_hmma,
                             cudaFuncAttributeMaxDynamicSharedMemorySize, DYNB);
        smem_set = 1;
    }

    k_pre<<<513, 256>>>(W, x, (const unsigned*)sy);
    k_sxp_hmma<<<dim3(64, 2), 256, DYNB>>>(sx);
    k_out<<<BATCH, 1024>>>((const int*)sy, out);
}